// round 12
// baseline (speedup 1.0000x reference)
#include <cuda_runtime.h>
#include <cuda_bf16.h>
#include <cstdint>

#define NNODES 512
#define EMAX   16384
#define PMAX   24

// ---------------------------------------------------------------------------
// Scratch (static __device__ globals; zero-initialized at module load).
// Mask/table contents are a pure function of edge_index and are rebuilt
// identically (idempotently) on every launch — no zeroing needed.
__device__ __align__(16) unsigned short g_M16 [NNODES * NNODES];
__device__ __align__(16) unsigned short g_MT16[NNODES * NNODES];
__device__ __align__(16) uint32_t g_Mb [NNODES * 16];
__device__ __align__(16) uint32_t g_MTb[NNODES * 16];
__device__ __align__(16) float    g_X  [EMAX * 64];
__device__ __align__(16) float    g_Y  [EMAX * 64];
__device__ __align__(16) char g_W1s_hi[4 * 32768];
__device__ __align__(16) char g_W1s_lo[4 * 32768];
__device__ __align__(16) char g_W2s_hi[4 * 16384];
__device__ __align__(16) char g_W2s_lo[4 * 16384];
__device__ unsigned long long g_arrive;

// ---------------------------------------------------------------------------
__device__ __forceinline__ uint32_t smem_u32(const void* p) {
    uint32_t a;
    asm("{ .reg .u64 t; cvta.to.shared.u64 t, %1; cvt.u32.u64 %0, t; }" : "=r"(a) : "l"(p));
    return a;
}
__device__ __forceinline__ void mma16816(float* c, const uint32_t* a,
                                         uint32_t b0, uint32_t b1) {
    asm("mma.sync.aligned.m16n8k16.row.col.f32.bf16.bf16.f32 "
        "{%0,%1,%2,%3}, {%4,%5,%6,%7}, {%8,%9}, {%0,%1,%2,%3};"
        : "+f"(c[0]), "+f"(c[1]), "+f"(c[2]), "+f"(c[3])
        : "r"(a[0]), "r"(a[1]), "r"(a[2]), "r"(a[3]), "r"(b0), "r"(b1));
}
__device__ __forceinline__ void ldmx4(uint32_t* r, uint32_t addr) {
    asm volatile("ldmatrix.sync.aligned.m8n8.x4.shared.b16 {%0,%1,%2,%3}, [%4];"
                 : "=r"(r[0]), "=r"(r[1]), "=r"(r[2]), "=r"(r[3]) : "r"(addr));
}
__device__ __forceinline__ uint32_t packbf(float x, float y) {
    __nv_bfloat162 t = __floats2bfloat162_rn(x, y);
    return *reinterpret_cast<uint32_t*>(&t);
}
__device__ __forceinline__ void split4(float4 v, uint2& hi, uint2& lo) {
    __nv_bfloat16 h0 = __float2bfloat16(v.x), h1 = __float2bfloat16(v.y);
    __nv_bfloat16 h2 = __float2bfloat16(v.z), h3 = __float2bfloat16(v.w);
    hi = make_uint2(packbf(__bfloat162float(h0), __bfloat162float(h1)),
                    packbf(__bfloat162float(h2), __bfloat162float(h3)));
    lo = make_uint2(packbf(v.x - __bfloat162float(h0), v.y - __bfloat162float(h1)),
                    packbf(v.z - __bfloat162float(h2), v.w - __bfloat162float(h3)));
}
__device__ __forceinline__ void cpasync16(uint32_t dst, const void* src) {
    asm volatile("cp.async.cg.shared.global [%0], [%1], 16;" :: "r"(dst), "l"(src) : "memory");
}
#define CP_COMMIT() asm volatile("cp.async.commit_group;" ::: "memory")
#define CP_WAIT0()  asm volatile("cp.async.wait_group 0;" ::: "memory")

// Global barrier: all CTAs co-resident (grid <= SM count). Monotonic counter;
// each call consumes one generation. Caller brackets with __syncthreads().
__device__ __forceinline__ void gbar(int tid, unsigned G) {
    __syncthreads();
    if (tid == 0) {
        __threadfence();
        unsigned long long t = atomicAdd(&g_arrive, 1ULL);
        unsigned long long target = (t / G + 1ULL) * G;
        unsigned long long v;
        do {
            asm volatile("ld.global.acquire.gpu.u64 %0, [%1];"
                         : "=l"(v) : "l"(&g_arrive));
        } while (v < target);
    }
    __syncthreads();
}

// ---------------------------------------------------------------------------
#define OFF_AHI   0u
#define OFF_ALO   32768u
#define OFF_B1HI  65536u
#define OFF_B1LO  98304u
#define XY_CHI    65536u
#define XY_CLO    81920u
#define XY_W1HI   98304u
#define XY_W1LO   106496u
#define XY_W2HI   114688u
#define XY_W2LO   122880u
#define OFF_B2    131072u
#define OFF_RED   65536u
#define OFF_PAIRS 196608u
#define OFF_CNT   (OFF_PAIRS + 128u * PMAX * 4u)
#define OFF_EI    (OFF_CNT + 512u)
#define SMEM_TOT  (OFF_EI + 1024u)

#define NTHREADS 512

__device__ __forceinline__ void stage_B1(uint32_t sb, int c, int tid) {
    #pragma unroll
    for (int i = 0; i < 8; i++) {
        int idx = tid + i * NTHREADS;
        int buf = idx >> 11, ii = idx & 2047;
        const char* src = (buf ? g_W1s_lo : g_W1s_hi) + (size_t)c * 32768 + (size_t)ii * 16;
        cpasync16(sb + OFF_B1HI + (uint32_t)buf * 32768u + (uint32_t)ii * 16u, src);
    }
}
__device__ __forceinline__ void stage_B2(uint32_t sb, int c, int b, int tid) {
    #pragma unroll
    for (int i = 0; i < 4; i++) {
        int idx = tid + i * NTHREADS;
        int buf = idx >> 10, ii = idx & 1023;
        const char* src = (buf ? g_W2s_lo : g_W2s_hi) + (size_t)c * 16384 + (size_t)ii * 16;
        cpasync16(sb + OFF_B2 + (uint32_t)b * 32768u + (uint32_t)buf * 16384u + (uint32_t)ii * 16u, src);
    }
}

__global__ __launch_bounds__(NTHREADS, 1)
void k_fused(const int* __restrict__ ei, const float* __restrict__ C,
             const float* __restrict__ WL1, const float* __restrict__ WL2,
             const float* __restrict__ W1,  const float* __restrict__ W2,
             float* __restrict__ out, int E) {
    extern __shared__ char smem[];
    uint32_t sb = smem_u32(smem);
    uint32_t* s_pairs = (uint32_t*)(smem + OFF_PAIRS);
    int*      s_cnt   = (int*)(smem + OFF_CNT);
    int*      s_ei    = (int*)(smem + OFF_EI);
    int tid = threadIdx.x;
    int wid = tid >> 5, lane = tid & 31;
    int wg  = wid & 7;
    int hi8 = wid >> 3;
    int rw = wg * 16;
    int e0 = blockIdx.x * 128;
    unsigned G = gridDim.x;

    // ===================== PHASE A0: scatter + prep ==========================
    if (tid < 128) {
        int i = ei[e0 + tid];
        int k = ei[E + e0 + tid];
        s_ei[tid] = i;
        s_ei[128 + tid] = k;
        g_M16 [i * NNODES + k] = (unsigned short)(e0 + tid);
        g_MT16[k * NNODES + i] = (unsigned short)(e0 + tid);
        atomicOr(&g_Mb [i * 16 + (k >> 5)], 1u << (k & 31));
        atomicOr(&g_MTb[k * 16 + (i >> 5)], 1u << (i & 31));
    } else if (tid < 256) {
        s_cnt[tid - 128] = 0;
    }

    // W1/W2 global pre-split, partitioned across the grid
    {
        int g = blockIdx.x * NTHREADS + tid;
        if (g < 16384) {
            int row = g >> 5, q = g & 31;
            float4 v = ((const float4*)W1)[g];
            uint2 hi, lo;
            split4(v, hi, lo);
            int c = row >> 7, r = row & 127;
            uint32_t off = (uint32_t)c * 32768u + (uint32_t)r * 256u +
                           (((uint32_t)q * 8u) ^ (((uint32_t)r & 7u) << 4));
            *(uint2*)(g_W1s_hi + off) = hi;
            *(uint2*)(g_W1s_lo + off) = lo;
        } else if (g < 24576) {
            int gg = g - 16384;
            int row = gg >> 7, q = gg & 127;
            float4 v = ((const float4*)W2)[gg];
            uint2 hi, lo;
            split4(v, hi, lo);
            int c = q >> 5, qq = q & 31;
            uint32_t off = (uint32_t)c * 16384u + (uint32_t)row * 256u +
                           (((uint32_t)qq * 8u) ^ (((uint32_t)row & 7u) << 4));
            *(uint2*)(g_W2s_hi + off) = hi;
            *(uint2*)(g_W2s_lo + off) = lo;
        }
    }

    // stage C tile once -> XY layout (128B rows) AND MLP A (256B rows)
    #pragma unroll
    for (int i = 0; i < 4; i++) {
        int idx = tid + i * NTHREADS;
        int r = idx >> 4, q = idx & 15;
        float4 v = ((const float4*)C)[(size_t)(e0 + r) * 16 + q];
        uint2 hi, lo;
        split4(v, hi, lo);
        uint32_t sw = (((uint32_t)q * 8u) ^ (((uint32_t)r & 7u) << 4));
        *(uint2*)(smem + XY_CHI + (uint32_t)r * 128u + sw)  = hi;
        *(uint2*)(smem + XY_CLO + (uint32_t)r * 128u + sw)  = lo;
        *(uint2*)(smem + OFF_AHI + (uint32_t)r * 256u + sw) = hi;
        *(uint2*)(smem + OFF_ALO + (uint32_t)r * 256u + sw) = lo;
    }
    // split W_L1/W_L2 locally
    #pragma unroll
    for (int i = 0; i < 4; i++) {
        int idx = tid + i * NTHREADS;
        int w = idx >> 10, ii = idx & 1023;
        int r = ii >> 4, q = ii & 15;
        float4 v = ((const float4*)(w ? WL2 : WL1))[ii];
        uint2 hi, lo;
        split4(v, hi, lo);
        uint32_t phys = (uint32_t)r * 128u + (((uint32_t)q * 8u) ^ (((uint32_t)r & 7u) << 4));
        *(uint2*)(smem + (w ? XY_W2HI : XY_W1HI) + phys) = hi;
        *(uint2*)(smem + (w ? XY_W2LO : XY_W1LO) + phys) = lo;
    }

    // ==================== BARRIER 1 (masks + weight prep visible) ============
    gbar(tid, G);

    // B2 chunk 0 staging: region doesn't overlap XY workspace -> fire now
    stage_B2(sb, 0, 0, tid);
    CP_COMMIT();

    // phase 1: pair extraction FIRST — its serial L2 chains overlap XY MMAs
    {
        int le = tid >> 2;
        int i = s_ei[le], k = s_ei[128 + le];
        int wb = (tid & 3) * 4;
        const uint32_t* mb  = &g_Mb [i * 16 + wb];
        const uint32_t* mtb = &g_MTb[k * 16 + wb];
        #pragma unroll
        for (int w4 = 0; w4 < 4; w4++) {
            uint32_t m = mb[w4] & mtb[w4];
            while (m) {
                int bb = __ffs(m) - 1;
                m &= m - 1;
                int j = (wb + w4) * 32 + bb;
                uint32_t e1 = g_M16 [i * NNODES + j];
                uint32_t e2 = g_MT16[k * NNODES + j];
                int p = atomicAdd(&s_cnt[le], 1);
                if (p < PMAX) s_pairs[le * PMAX + p] = e1 | (e2 << 16);
            }
        }
    }

    int l7 = lane & 7;
    int sel = lane >> 3;
    uint32_t xorv = (uint32_t)l7 << 4;
    uint32_t bKof = (uint32_t)(sel & 1) * 16u;

    // XY GEMM: warp pair splits the 4 n16-tiles
    {
        uint32_t aRow = (uint32_t)(rw + (sel & 1) * 8 + l7) * 128u;
        uint32_t aKof = (uint32_t)(sel >> 1) * 16u;
        uint32_t bRow = (uint32_t)((sel >> 1) * 8 + l7) * 128u;

        float dX[4][4], dY[4][4];
        #pragma unroll
        for (int i = 0; i < 4; i++)
            #pragma unroll
            for (int j = 0; j < 4; j++) { dX[i][j] = 0.f; dY[i][j] = 0.f; }

        #pragma unroll
        for (int ks = 0; ks < 4; ks++) {
            uint32_t kb = (uint32_t)ks * 32u;
            uint32_t ch[4], cl[4];
            ldmx4(ch, sb + XY_CHI + aRow + ((kb + aKof) ^ xorv));
            ldmx4(cl, sb + XY_CLO + aRow + ((kb + aKof) ^ xorv));
            #pragma unroll
            for (int j = 0; j < 2; j++) {
                int np = hi8 * 2 + j;
                uint32_t off = (uint32_t)np * 2048u + bRow + ((kb + bKof) ^ xorv);
                uint32_t b1h[4], b1l[4], b2h[4], b2l[4];
                ldmx4(b1h, sb + XY_W1HI + off);
                ldmx4(b1l, sb + XY_W1LO + off);
                ldmx4(b2h, sb + XY_W2HI + off);
                ldmx4(b2l, sb + XY_W2LO + off);
                mma16816(dX[2 * j],     ch, b1h[0], b1h[1]);
                mma16816(dX[2 * j + 1], ch, b1h[2], b1h[3]);
                mma16816(dX[2 * j],     ch, b1l[0], b1l[1]);
                mma16816(dX[2 * j + 1], ch, b1l[2], b1l[3]);
                mma16816(dX[2 * j],     cl, b1h[0], b1h[1]);
                mma16816(dX[2 * j + 1], cl, b1h[2], b1h[3]);
                mma16816(dY[2 * j],     ch, b2h[0], b2h[1]);
                mma16816(dY[2 * j + 1], ch, b2h[2], b2h[3]);
                mma16816(dY[2 * j],     ch, b2l[0], b2l[1]);
                mma16816(dY[2 * j + 1], ch, b2l[2], b2l[3]);
                mma16816(dY[2 * j],     cl, b2h[0], b2h[1]);
                mma16816(dY[2 * j + 1], cl, b2h[2], b2h[3]);
            }
        }

        int r0 = e0 + rw + (lane >> 2);
        int c0 = (lane & 3) * 2;
        #pragma unroll
        for (int t = 0; t < 4; t++) {
            int ntc = hi8 * 4 + t;
            *(float2*)(g_X + (size_t)r0 * 64 + ntc * 8 + c0)       = make_float2(dX[t][0], dX[t][1]);
            *(float2*)(g_X + (size_t)(r0 + 8) * 64 + ntc * 8 + c0) = make_float2(dX[t][2], dX[t][3]);
            *(float2*)(g_Y + (size_t)r0 * 64 + ntc * 8 + c0)       = make_float2(dY[t][0], dY[t][1]);
            *(float2*)(g_Y + (size_t)(r0 + 8) * 64 + ntc * 8 + c0) = make_float2(dY[t][2], dY[t][3]);
        }
    }

    // XY smem reads retired -> B1 chunk 0 staging can overwrite XY workspace
    __syncthreads();
    stage_B1(sb, 0, tid);
    CP_COMMIT();

    // ==================== BARRIER 2 (g_X / g_Y visible) ======================
    gbar(tid, G);

    // phase 2: path products -> A cols 64..127 (8 edges/warp, 4-interleave)
    {
        const float2* Xb = (const float2*)g_X;
        const float2* Yb = (const float2*)g_Y;
        for (int t = 0; t < 8; t += 4) {
            int n[4];
            float2 ac[4];
            int nm = 0;
            #pragma unroll
            for (int u = 0; u < 4; u++) {
                int cn = s_cnt[wid * 8 + t + u];
                n[u] = cn < PMAX ? cn : PMAX;
                nm = n[u] > nm ? n[u] : nm;
                ac[u] = make_float2(0.f, 0.f);
            }
            for (int p = 0; p < nm; p++) {
                #pragma unroll
                for (int u = 0; u < 4; u++) {
                    if (p < n[u]) {
                        uint32_t pr = s_pairs[(wid * 8 + t + u) * PMAX + p];
                        float2 x = Xb[(size_t)(pr & 0xffffu) * 32 + lane];
                        float2 y = Yb[(size_t)(pr >> 16) * 32 + lane];
                        ac[u].x = fmaf(x.x, y.x, ac[u].x);
                        ac[u].y = fmaf(x.y, y.y, ac[u].y);
                    }
                }
            }
            #pragma unroll
            for (int u = 0; u < 4; u++) {
                int le = wid * 8 + t + u;
                float2 acc = ac[u];
                __nv_bfloat16 h0 = __float2bfloat16(acc.x), h1 = __float2bfloat16(acc.y);
                uint32_t hi = packbf(__bfloat162float(h0), __bfloat162float(h1));
                uint32_t lo = packbf(acc.x - __bfloat162float(h0), acc.y - __bfloat162float(h1));
                uint32_t kb = 128u + (uint32_t)lane * 4u;
                uint32_t phys = (uint32_t)le * 256u + (kb ^ (((uint32_t)le & 7u) << 4));
                *(uint32_t*)(smem + OFF_AHI + phys) = hi;
                *(uint32_t*)(smem + OFF_ALO + phys) = lo;
            }
        }
    }
    CP_WAIT0();
    __syncthreads();

    // MLP main loop — warp pair splits N of MMA1 (= K of MMA2)
    uint32_t aRow = (uint32_t)(rw + (sel & 1) * 8 + l7) * 256u;
    uint32_t aKof = (uint32_t)(sel >> 1) * 16u;
    uint32_t bRowBase = (uint32_t)((sel >> 1) * 8 + l7) * 256u;

    float d2a[8][4];
    #pragma unroll
    for (int i = 0; i < 8; i++)
        #pragma unroll
        for (int j = 0; j < 4; j++) d2a[i][j] = 0.f;

    for (int c = 0; c < 4; c++) {
        float d1[8][4];
        #pragma unroll
        for (int i = 0; i < 8; i++)
            #pragma unroll
            for (int j = 0; j < 4; j++) d1[i][j] = 0.f;

        #pragma unroll
        for (int ks = 0; ks < 8; ks++) {
            uint32_t kb = (uint32_t)ks * 32u;
            uint32_t ah[4], al[4];
            ldmx4(ah, sb + OFF_AHI + aRow + ((kb + aKof) ^ xorv));
            ldmx4(al, sb + OFF_ALO + aRow + ((kb + aKof) ^ xorv));
            #pragma unroll
            for (int j = 0; j < 4; j++) {
                int np = hi8 * 4 + j;
                uint32_t off = (uint32_t)np * 4096u + bRowBase + ((kb + bKof) ^ xorv);
                uint32_t bh[4], bl[4];
                ldmx4(bh, sb + OFF_B1HI + off);
                ldmx4(bl, sb + OFF_B1LO + off);
                mma16816(d1[2 * j],     ah, bh[0], bh[1]);
                mma16816(d1[2 * j + 1], ah, bh[2], bh[3]);
                mma16816(d1[2 * j],     ah, bl[0], bl[1]);
                mma16816(d1[2 * j + 1], ah, bl[2], bl[3]);
                mma16816(d1[2 * j],     al, bh[0], bh[1]);
                mma16816(d1[2 * j + 1], al, bh[2], bh[3]);
            }
        }

        __syncthreads();
        if (c < 3) {
            stage_B1(sb, c + 1, tid);
            stage_B2(sb, c + 1, (c + 1) & 1, tid);
            CP_COMMIT();
        }

        uint32_t b2h_base = sb + OFF_B2 + (uint32_t)(c & 1) * 32768u;
        uint32_t b2l_base = b2h_base + 16384u;
        #pragma unroll
        for (int j = 0; j < 4; j++) {
            int kt = hi8 * 4 + j;
            float va0 = fmaxf(d1[2 * j][0], 0.f), va1 = fmaxf(d1[2 * j][1], 0.f);
            float va2 = fmaxf(d1[2 * j][2], 0.f), va3 = fmaxf(d1[2 * j][3], 0.f);
            float vb0 = fmaxf(d1[2 * j + 1][0], 0.f), vb1 = fmaxf(d1[2 * j + 1][1], 0.f);
            float vb2 = fmaxf(d1[2 * j + 1][2], 0.f), vb3 = fmaxf(d1[2 * j + 1][3], 0.f);
            float ha0 = __bfloat162float(__float2bfloat16(va0));
            float ha1 = __bfloat162float(__float2bfloat16(va1));
            float ha2 = __bfloat162float(__float2bfloat16(va2));
            float ha3 = __bfloat162float(__float2bfloat16(va3));
            float hb0 = __bfloat162float(__float2bfloat16(vb0));
            float hb1 = __bfloat162float(__float2bfloat16(vb1));
            float hb2 = __bfloat162float(__float2bfloat16(vb2));
            float hb3 = __bfloat162float(__float2bfloat16(vb3));
            uint32_t ah[4] = { packbf(ha0, ha1), packbf(ha2, ha3),
                               packbf(hb0, hb1), packbf(hb2, hb3) };
            uint32_t al[4] = { packbf(va0 - ha0, va1 - ha1), packbf(va2 - ha2, va3 - ha3),
                               packbf(vb0 - hb0, vb1 - hb1), packbf(vb2 - hb2, vb3 - hb3) };
            uint32_t kb = (uint32_t)kt * 32u;
            #pragma unroll
            for (int np = 0; np < 4; np++) {
                uint32_t bh[4], bl[4];
                uint32_t off = (uint32_t)np * 4096u + bRowBase + ((kb + bKof) ^ xorv);
                ldmx4(bh, b2h_base + off);
                ldmx4(bl, b2l_base + off);
                mma16816(d2a[2 * np],     ah, bh[0], bh[1]);
                mma16816(d2a[2 * np + 1], ah, bh[2], bh[3]);
                mma16816(d2a[2 * np],     ah, bl[0], bl[1]);
                mma16816(d2a[2 * np + 1], ah, bl[2], bl[3]);
                mma16816(d2a[2 * np],     al, bh[0], bh[1]);
                mma16816(d2a[2 * np + 1], al, bh[2], bh[3]);
            }
        }
        if (c < 3) { CP_WAIT0(); __syncthreads(); }
    }

    // cross-warp reduction of d2a pairs (wg, hi8) via SMEM, then write out
    __syncthreads();
    if (hi8 == 1) {
        float* red = (float*)(smem + OFF_RED) + (size_t)wg * 1024 + lane;
        #pragma unroll
        for (int i = 0; i < 8; i++)
            #pragma unroll
            for (int j = 0; j < 4; j++)
                red[(i * 4 + j) * 32] = d2a[i][j];
    }
    __syncthreads();
    if (hi8 == 0) {
        const float* red = (const float*)(smem + OFF_RED) + (size_t)wg * 1024 + lane;
        #pragma unroll
        for (int i = 0; i < 8; i++)
            #pragma unroll
            for (int j = 0; j < 4; j++)
                d2a[i][j] += red[(i * 4 + j) * 32];

        int r0 = e0 + rw + (lane >> 2);
        int c0 = (lane & 3) * 2;
        #pragma unroll
        for (int ntc = 0; ntc < 8; ntc++) {
            *(float2*)(out + (size_t)r0 * 64 + ntc * 8 + c0)       = make_float2(d2a[ntc][0], d2a[ntc][1]);
            *(float2*)(out + (size_t)(r0 + 8) * 64 + ntc * 8 + c0) = make_float2(d2a[ntc][2], d2a[ntc][3]);
        }
    }
}

// ---------------------------------------------------------------------------
extern "C" void kernel_launch(void* const* d_in, const int* in_sizes, int n_in,
                              void* d_out, int out_size) {
    const int*   edge_index = (const int*)  d_in[0];   // [2, E]
    const float* C          = (const float*)d_in[1];   // [E, 64]
    const float* W_L1       = (const float*)d_in[3];   // [64, 64]
    const float* W_L2       = (const float*)d_in[4];   // [64, 64]
    const float* W_mlp1     = (const float*)d_in[5];   // [512, 128]
    const float* W_mlp2     = (const float*)d_in[6];   // [64, 512]
    float* out = (float*)d_out;                        // [E, 64]

    int E = in_sizes[0] / 2;                           // 16384

    cudaFuncSetAttribute(k_fused, cudaFuncAttributeMaxDynamicSharedMemorySize, SMEM_TOT);
    k_fused<<<E / 128, NTHREADS, SMEM_TOT>>>(edge_index, C, W_L1, W_L2,
                                             W_mlp1, W_mlp2, out, E);
}

// round 17
// speedup vs baseline: 1.2057x; 1.2057x over previous
#include <cuda_runtime.h>
#include <cuda_fp16.h>
#include <cstdint>

#define NNODES 512
#define EMAX   16384
#define PMAX   24

// ---------------------------------------------------------------------------
// Scratch (static __device__ globals; zero-initialized at module load).
// Mask/table contents are a pure function of edge_index and are rebuilt
// identically (idempotently) on every launch — no zeroing needed.
__device__ __align__(16) unsigned short g_M16 [NNODES * NNODES];
__device__ __align__(16) unsigned short g_MT16[NNODES * NNODES];
__device__ __align__(16) uint32_t g_Mb [NNODES * 16];
__device__ __align__(16) uint32_t g_MTb[NNODES * 16];
__device__ __align__(16) float    g_X  [EMAX * 64];
__device__ __align__(16) float    g_Y  [EMAX * 64];
__device__ __align__(16) char g_W1s[4 * 32768];   // W1 fp16, 4 chunks x (128 rows x 256B)
__device__ __align__(16) char g_W2s[4 * 16384];   // W2 fp16, 4 chunks x (64 rows x 256B)
__device__ unsigned long long g_arrive;

// ---------------------------------------------------------------------------
__device__ __forceinline__ uint32_t smem_u32(const void* p) {
    uint32_t a;
    asm("{ .reg .u64 t; cvta.to.shared.u64 t, %1; cvt.u32.u64 %0, t; }" : "=r"(a) : "l"(p));
    return a;
}
// mma.sync m16n8k16 row.col fp16 -> f32 accumulate
__device__ __forceinline__ void mma16816(float* c, const uint32_t* a,
                                         uint32_t b0, uint32_t b1) {
    asm("mma.sync.aligned.m16n8k16.row.col.f32.f16.f16.f32 "
        "{%0,%1,%2,%3}, {%4,%5,%6,%7}, {%8,%9}, {%0,%1,%2,%3};"
        : "+f"(c[0]), "+f"(c[1]), "+f"(c[2]), "+f"(c[3])
        : "r"(a[0]), "r"(a[1]), "r"(a[2]), "r"(a[3]), "r"(b0), "r"(b1));
}
__device__ __forceinline__ void ldmx4(uint32_t* r, uint32_t addr) {
    asm volatile("ldmatrix.sync.aligned.m8n8.x4.shared.b16 {%0,%1,%2,%3}, [%4];"
                 : "=r"(r[0]), "=r"(r[1]), "=r"(r[2]), "=r"(r[3]) : "r"(addr));
}
__device__ __forceinline__ uint32_t packh(float x, float y) {
    __half2 t = __floats2half2_rn(x, y);
    return *reinterpret_cast<uint32_t*>(&t);
}
// fp16 hi/lo split of a float4
__device__ __forceinline__ void split4h(float4 v, uint2& hi, uint2& lo) {
    __half h0 = __float2half_rn(v.x), h1 = __float2half_rn(v.y);
    __half h2 = __float2half_rn(v.z), h3 = __float2half_rn(v.w);
    hi = make_uint2(packh(__half2float(h0), __half2float(h1)),
                    packh(__half2float(h2), __half2float(h3)));
    lo = make_uint2(packh(v.x - __half2float(h0), v.y - __half2float(h1)),
                    packh(v.z - __half2float(h2), v.w - __half2float(h3)));
}
__device__ __forceinline__ void cpasync16(uint32_t dst, const void* src) {
    asm volatile("cp.async.cg.shared.global [%0], [%1], 16;" :: "r"(dst), "l"(src) : "memory");
}
#define CP_COMMIT() asm volatile("cp.async.commit_group;" ::: "memory")
#define CP_WAIT0()  asm volatile("cp.async.wait_group 0;" ::: "memory")

// Global barrier: all CTAs co-resident (grid <= SM count).
__device__ __forceinline__ void gbar(int tid, unsigned G) {
    __syncthreads();
    if (tid == 0) {
        __threadfence();
        unsigned long long t = atomicAdd(&g_arrive, 1ULL);
        unsigned long long target = (t / G + 1ULL) * G;
        unsigned long long v;
        do {
            asm volatile("ld.global.acquire.gpu.u64 %0, [%1];"
                         : "=l"(v) : "l"(&g_arrive));
        } while (v < target);
    }
    __syncthreads();
}

// ---------------------------------------------------------------------------
#define OFF_AHI   0u
#define OFF_ALO   32768u
#define OFF_B1    65536u                         // fp16 W1 chunk, 32KB
#define XY_CHI    98304u
#define XY_CLO    114688u
#define XY_W1HI   131072u
#define XY_W1LO   139264u
#define XY_W2HI   147456u
#define XY_W2LO   155648u
#define OFF_B2    163840u                        // 2 buffers x 16KB
#define OFF_RED   98304u                         // reuses XY region (retired)
#define OFF_PAIRS 196608u
#define OFF_CNT   (OFF_PAIRS + 128u * PMAX * 4u)
#define OFF_EI    (OFF_CNT + 512u)
#define SMEM_TOT  (OFF_EI + 1024u)

#define NTHREADS 512

__device__ __forceinline__ void stage_B1(uint32_t sb, int c, int tid) {
    #pragma unroll
    for (int i = 0; i < 4; i++) {
        int ii = tid + i * NTHREADS;             // 0..2047
        cpasync16(sb + OFF_B1 + (uint32_t)ii * 16u,
                  g_W1s + (size_t)c * 32768 + (size_t)ii * 16);
    }
}
__device__ __forceinline__ void stage_B2(uint32_t sb, int c, int b, int tid) {
    #pragma unroll
    for (int i = 0; i < 2; i++) {
        int ii = tid + i * NTHREADS;             // 0..1023
        cpasync16(sb + OFF_B2 + (uint32_t)b * 16384u + (uint32_t)ii * 16u,
                  g_W2s + (size_t)c * 16384 + (size_t)ii * 16);
    }
}

__global__ __launch_bounds__(NTHREADS, 1)
void k_fused(const int* __restrict__ ei, const float* __restrict__ C,
             const float* __restrict__ WL1, const float* __restrict__ WL2,
             const float* __restrict__ W1,  const float* __restrict__ W2,
             float* __restrict__ out, int E) {
    extern __shared__ char smem[];
    uint32_t sb = smem_u32(smem);
    uint32_t* s_pairs = (uint32_t*)(smem + OFF_PAIRS);
    int*      s_cnt   = (int*)(smem + OFF_CNT);
    int*      s_ei    = (int*)(smem + OFF_EI);
    int tid = threadIdx.x;
    int wid = tid >> 5, lane = tid & 31;
    int wg  = wid & 7;
    int hi8 = wid >> 3;
    int rw = wg * 16;
    int e0 = blockIdx.x * 128;
    unsigned G = gridDim.x;

    // ===================== PHASE A0: scatter + prep ==========================
    if (tid < 128) {
        int i = ei[e0 + tid];
        int k = ei[E + e0 + tid];
        s_ei[tid] = i;
        s_ei[128 + tid] = k;
        g_M16 [i * NNODES + k] = (unsigned short)(e0 + tid);
        g_MT16[k * NNODES + i] = (unsigned short)(e0 + tid);
        atomicOr(&g_Mb [i * 16 + (k >> 5)], 1u << (k & 31));
        atomicOr(&g_MTb[k * 16 + (i >> 5)], 1u << (i & 31));
    } else if (tid < 256) {
        s_cnt[tid - 128] = 0;
    }

    // W1/W2 global fp16 conversion, partitioned across the grid
    {
        int g = blockIdx.x * NTHREADS + tid;
        if (g < 16384) {
            int row = g >> 5, q = g & 31;
            float4 v = ((const float4*)W1)[g];
            uint2 h = make_uint2(packh(v.x, v.y), packh(v.z, v.w));
            int c = row >> 7, r = row & 127;
            uint32_t off = (uint32_t)c * 32768u + (uint32_t)r * 256u +
                           (((uint32_t)q * 8u) ^ (((uint32_t)r & 7u) << 4));
            *(uint2*)(g_W1s + off) = h;
        } else if (g < 24576) {
            int gg = g - 16384;
            int row = gg >> 7, q = gg & 127;
            float4 v = ((const float4*)W2)[gg];
            uint2 h = make_uint2(packh(v.x, v.y), packh(v.z, v.w));
            int c = q >> 5, qq = q & 31;
            uint32_t off = (uint32_t)c * 16384u + (uint32_t)row * 256u +
                           (((uint32_t)qq * 8u) ^ (((uint32_t)row & 7u) << 4));
            *(uint2*)(g_W2s + off) = h;
        }
    }

    // stage C tile once -> XY layout (128B rows) AND MLP A (256B rows), fp16 hi/lo
    #pragma unroll
    for (int i = 0; i < 4; i++) {
        int idx = tid + i * NTHREADS;
        int r = idx >> 4, q = idx & 15;
        float4 v = ((const float4*)C)[(size_t)(e0 + r) * 16 + q];
        uint2 hi, lo;
        split4h(v, hi, lo);
        uint32_t sw = (((uint32_t)q * 8u) ^ (((uint32_t)r & 7u) << 4));
        *(uint2*)(smem + XY_CHI + (uint32_t)r * 128u + sw)  = hi;
        *(uint2*)(smem + XY_CLO + (uint32_t)r * 128u + sw)  = lo;
        *(uint2*)(smem + OFF_AHI + (uint32_t)r * 256u + sw) = hi;
        *(uint2*)(smem + OFF_ALO + (uint32_t)r * 256u + sw) = lo;
    }
    // split W_L1/W_L2 locally (fp16 hi/lo — XY keeps 3-pass precision)
    #pragma unroll
    for (int i = 0; i < 4; i++) {
        int idx = tid + i * NTHREADS;
        int w = idx >> 10, ii = idx & 1023;
        int r = ii >> 4, q = ii & 15;
        float4 v = ((const float4*)(w ? WL2 : WL1))[ii];
        uint2 hi, lo;
        split4h(v, hi, lo);
        uint32_t phys = (uint32_t)r * 128u + (((uint32_t)q * 8u) ^ (((uint32_t)r & 7u) << 4));
        *(uint2*)(smem + (w ? XY_W2HI : XY_W1HI) + phys) = hi;
        *(uint2*)(smem + (w ? XY_W2LO : XY_W1LO) + phys) = lo;
    }

    // ==================== BARRIER 1 (masks + fp16 weights visible) ===========
    gbar(tid, G);

    // B1/B2 chunk-0 staging: regions don't overlap XY workspace -> fire now
    stage_B1(sb, 0, tid);
    stage_B2(sb, 0, 0, tid);
    CP_COMMIT();

    // phase 1: pair extraction (4 threads per edge, 4 mask words each)
    {
        int le = tid >> 2;
        int i = s_ei[le], k = s_ei[128 + le];
        int wb = (tid & 3) * 4;
        const uint32_t* mb  = &g_Mb [i * 16 + wb];
        const uint32_t* mtb = &g_MTb[k * 16 + wb];
        #pragma unroll
        for (int w4 = 0; w4 < 4; w4++) {
            uint32_t m = mb[w4] & mtb[w4];
            while (m) {
                int bb = __ffs(m) - 1;
                m &= m - 1;
                int j = (wb + w4) * 32 + bb;
                uint32_t e1 = g_M16 [i * NNODES + j];
                uint32_t e2 = g_MT16[k * NNODES + j];
                int p = atomicAdd(&s_cnt[le], 1);
                if (p < PMAX) s_pairs[le * PMAX + p] = e1 | (e2 << 16);
            }
        }
    }

    int l7 = lane & 7;
    int sel = lane >> 3;
    uint32_t xorv = (uint32_t)l7 << 4;
    uint32_t bKof = (uint32_t)(sel & 1) * 16u;

    // XY GEMM (fp16x3): warp pair splits the 4 n16-tiles
    {
        uint32_t aRow = (uint32_t)(rw + (sel & 1) * 8 + l7) * 128u;
        uint32_t aKof = (uint32_t)(sel >> 1) * 16u;
        uint32_t bRow = (uint32_t)((sel >> 1) * 8 + l7) * 128u;

        float dX[4][4], dY[4][4];
        #pragma unroll
        for (int i = 0; i < 4; i++)
            #pragma unroll
            for (int j = 0; j < 4; j++) { dX[i][j] = 0.f; dY[i][j] = 0.f; }

        #pragma unroll
        for (int ks = 0; ks < 4; ks++) {
            uint32_t kb = (uint32_t)ks * 32u;
            uint32_t ch[4], cl[4];
            ldmx4(ch, sb + XY_CHI + aRow + ((kb + aKof) ^ xorv));
            ldmx4(cl, sb + XY_CLO + aRow + ((kb + aKof) ^ xorv));
            #pragma unroll
            for (int j = 0; j < 2; j++) {
                int np = hi8 * 2 + j;
                uint32_t off = (uint32_t)np * 2048u + bRow + ((kb + bKof) ^ xorv);
                uint32_t b1h[4], b1l[4], b2h[4], b2l[4];
                ldmx4(b1h, sb + XY_W1HI + off);
                ldmx4(b1l, sb + XY_W1LO + off);
                ldmx4(b2h, sb + XY_W2HI + off);
                ldmx4(b2l, sb + XY_W2LO + off);
                mma16816(dX[2 * j],     ch, b1h[0], b1h[1]);
                mma16816(dX[2 * j + 1], ch, b1h[2], b1h[3]);
                mma16816(dX[2 * j],     ch, b1l[0], b1l[1]);
                mma16816(dX[2 * j + 1], ch, b1l[2], b1l[3]);
                mma16816(dX[2 * j],     cl, b1h[0], b1h[1]);
                mma16816(dX[2 * j + 1], cl, b1h[2], b1h[3]);
                mma16816(dY[2 * j],     ch, b2h[0], b2h[1]);
                mma16816(dY[2 * j + 1], ch, b2h[2], b2h[3]);
                mma16816(dY[2 * j],     ch, b2l[0], b2l[1]);
                mma16816(dY[2 * j + 1], ch, b2l[2], b2l[3]);
                mma16816(dY[2 * j],     cl, b2h[0], b2h[1]);
                mma16816(dY[2 * j + 1], cl, b2h[2], b2h[3]);
            }
        }

        int r0 = e0 + rw + (lane >> 2);
        int c0 = (lane & 3) * 2;
        #pragma unroll
        for (int t = 0; t < 4; t++) {
            int ntc = hi8 * 4 + t;
            *(float2*)(g_X + (size_t)r0 * 64 + ntc * 8 + c0)       = make_float2(dX[t][0], dX[t][1]);
            *(float2*)(g_X + (size_t)(r0 + 8) * 64 + ntc * 8 + c0) = make_float2(dX[t][2], dX[t][3]);
            *(float2*)(g_Y + (size_t)r0 * 64 + ntc * 8 + c0)       = make_float2(dY[t][0], dY[t][1]);
            *(float2*)(g_Y + (size_t)(r0 + 8) * 64 + ntc * 8 + c0) = make_float2(dY[t][2], dY[t][3]);
        }
    }

    // ==================== BARRIER 2 (g_X / g_Y visible) ======================
    gbar(tid, G);

    // phase 2: path products -> A cols 64..127 (8 edges/warp, 4-interleave)
    {
        const float2* Xb = (const float2*)g_X;
        const float2* Yb = (const float2*)g_Y;
        for (int t = 0; t < 8; t += 4) {
            int n[4];
            float2 ac[4];
            int nm = 0;
            #pragma unroll
            for (int u = 0; u < 4; u++) {
                int cn = s_cnt[wid * 8 + t + u];
                n[u] = cn < PMAX ? cn : PMAX;
                nm = n[u] > nm ? n[u] : nm;
                ac[u] = make_float2(0.f, 0.f);
            }
            for (int p = 0; p < nm; p++) {
                #pragma unroll
                for (int u = 0; u < 4; u++) {
                    if (p < n[u]) {
                        uint32_t pr = s_pairs[(wid * 8 + t + u) * PMAX + p];
                        float2 x = Xb[(size_t)(pr & 0xffffu) * 32 + lane];
                        float2 y = Yb[(size_t)(pr >> 16) * 32 + lane];
                        ac[u].x = fmaf(x.x, y.x, ac[u].x);
                        ac[u].y = fmaf(x.y, y.y, ac[u].y);
                    }
                }
            }
            #pragma unroll
            for (int u = 0; u < 4; u++) {
                int le = wid * 8 + t + u;
                float2 acc = ac[u];
                __half h0 = __float2half_rn(acc.x), h1 = __float2half_rn(acc.y);
                uint32_t hi = packh(__half2float(h0), __half2float(h1));
                uint32_t lo = packh(acc.x - __half2float(h0), acc.y - __half2float(h1));
                uint32_t kb = 128u + (uint32_t)lane * 4u;
                uint32_t phys = (uint32_t)le * 256u + (kb ^ (((uint32_t)le & 7u) << 4));
                *(uint32_t*)(smem + OFF_AHI + phys) = hi;
                *(uint32_t*)(smem + OFF_ALO + phys) = lo;
            }
        }
    }
    CP_WAIT0();
    __syncthreads();

    // MLP main loop (fp16 2-pass) — warp pair splits N of MMA1 (= K of MMA2)
    uint32_t aRow = (uint32_t)(rw + (sel & 1) * 8 + l7) * 256u;
    uint32_t aKof = (uint32_t)(sel >> 1) * 16u;
    uint32_t bRowBase = (uint32_t)((sel >> 1) * 8 + l7) * 256u;

    float d2a[8][4];
    #pragma unroll
    for (int i = 0; i < 8; i++)
        #pragma unroll
        for (int j = 0; j < 4; j++) d2a[i][j] = 0.f;

    for (int c = 0; c < 4; c++) {
        float d1[8][4];
        #pragma unroll
        for (int i = 0; i < 8; i++)
            #pragma unroll
            for (int j = 0; j < 4; j++) d1[i][j] = 0.f;

        // MMA1: d1 += A @ W1c^T  (A fp16 hi/lo, W1 single fp16)
        #pragma unroll
        for (int ks = 0; ks < 8; ks++) {
            uint32_t kb = (uint32_t)ks * 32u;
            uint32_t ah[4], al[4];
            ldmx4(ah, sb + OFF_AHI + aRow + ((kb + aKof) ^ xorv));
            ldmx4(al, sb + OFF_ALO + aRow + ((kb + aKof) ^ xorv));
            #pragma unroll
            for (int j = 0; j < 4; j++) {
                int np = hi8 * 4 + j;
                uint32_t off = (uint32_t)np * 4096u + bRowBase + ((kb + bKof) ^ xorv);
                uint32_t bh[4];
                ldmx4(bh, sb + OFF_B1 + off);
                mma16816(d1[2 * j],     ah, bh[0], bh[1]);
                mma16816(d1[2 * j + 1], ah, bh[2], bh[3]);
                mma16816(d1[2 * j],     al, bh[0], bh[1]);
                mma16816(d1[2 * j + 1], al, bh[2], bh[3]);
            }
        }

        __syncthreads();
        if (c < 3) {
            stage_B1(sb, c + 1, tid);
            stage_B2(sb, c + 1, (c + 1) & 1, tid);
            CP_COMMIT();
        }

        // MMA2: d2a += relu(d1) @ W2c^T  (H fp16 hi/lo, W2 single fp16)
        uint32_t b2base = sb + OFF_B2 + (uint32_t)(c & 1) * 16384u;
        #pragma unroll
        for (int j = 0; j < 4; j++) {
            int kt = hi8 * 4 + j;
            float va0 = fmaxf(d1[2 * j][0], 0.f), va1 = fmaxf(d1[2 * j][1], 0.f);
            float va2 = fmaxf(d1[2 * j][2], 0.f), va3 = fmaxf(d1[2 * j][3], 0.f);
            float vb0 = fmaxf(d1[2 * j + 1][0], 0.f), vb1 = fmaxf(d1[2 * j + 1][1], 0.f);
            float vb2 = fmaxf(d1[2 * j + 1][2], 0.f), vb3 = fmaxf(d1[2 * j + 1][3], 0.f);
            float ha0 = __half2float(__float2half_rn(va0));
            float ha1 = __half2float(__float2half_rn(va1));
            float ha2 = __half2float(__float2half_rn(va2));
            float ha3 = __half2float(__float2half_rn(va3));
            float hb0 = __half2float(__float2half_rn(vb0));
            float hb1 = __half2float(__float2half_rn(vb1));
            float hb2 = __half2float(__float2half_rn(vb2));
            float hb3 = __half2float(__float2half_rn(vb3));
            uint32_t ah[4] = { packh(ha0, ha1), packh(ha2, ha3),
                               packh(hb0, hb1), packh(hb2, hb3) };
            uint32_t al[4] = { packh(va0 - ha0, va1 - ha1), packh(va2 - ha2, va3 - ha3),
                               packh(vb0 - hb0, vb1 - hb1), packh(vb2 - hb2, vb3 - hb3) };
            uint32_t kb = (uint32_t)kt * 32u;
            #pragma unroll
            for (int np = 0; np < 4; np++) {
                uint32_t bh[4];
                uint32_t off = (uint32_t)np * 4096u + bRowBase + ((kb + bKof) ^ xorv);
                ldmx4(bh, b2base + off);
                mma16816(d2a[2 * np],     ah, bh[0], bh[1]);
                mma16816(d2a[2 * np + 1], ah, bh[2], bh[3]);
                mma16816(d2a[2 * np],     al, bh[0], bh[1]);
                mma16816(d2a[2 * np + 1], al, bh[2], bh[3]);
            }
        }
        if (c < 3) { CP_WAIT0(); __syncthreads(); }
    }

    // cross-warp reduction of d2a pairs (wg, hi8) via SMEM, then write out
    __syncthreads();
    if (hi8 == 1) {
        float* red = (float*)(smem + OFF_RED) + (size_t)wg * 1024 + lane;
        #pragma unroll
        for (int i = 0; i < 8; i++)
            #pragma unroll
            for (int j = 0; j < 4; j++)
                red[(i * 4 + j) * 32] = d2a[i][j];
    }
    __syncthreads();
    if (hi8 == 0) {
        const float* red = (const float*)(smem + OFF_RED) + (size_t)wg * 1024 + lane;
        #pragma unroll
        for (int i = 0; i < 8; i++)
            #pragma unroll
            for (int j = 0; j < 4; j++)
                d2a[i][j] += red[(i * 4 + j) * 32];

        int r0 = e0 + rw + (lane >> 2);
        int c0 = (lane & 3) * 2;
        #pragma unroll
        for (int ntc = 0; ntc < 8; ntc++) {
            *(float2*)(out + (size_t)r0 * 64 + ntc * 8 + c0)       = make_float2(d2a[ntc][0], d2a[ntc][1]);
            *(float2*)(out + (size_t)(r0 + 8) * 64 + ntc * 8 + c0) = make_float2(d2a[ntc][2], d2a[ntc][3]);
        }
    }
}

// ---------------------------------------------------------------------------
extern "C" void kernel_launch(void* const* d_in, const int* in_sizes, int n_in,
                              void* d_out, int out_size) {
    const int*   edge_index = (const int*)  d_in[0];   // [2, E]
    const float* C          = (const float*)d_in[1];   // [E, 64]
    const float* W_L1       = (const float*)d_in[3];   // [64, 64]
    const float* W_L2       = (const float*)d_in[4];   // [64, 64]
    const float* W_mlp1     = (const float*)d_in[5];   // [512, 128]
    const float* W_mlp2     = (const float*)d_in[6];   // [64, 512]
    float* out = (float*)d_out;                        // [E, 64]

    int E = in_sizes[0] / 2;                           // 16384

    cudaFuncSetAttribute(k_fused, cudaFuncAttributeMaxDynamicSharedMemorySize, SMEM_TOT);
    k_fused<<<E / 128, NTHREADS, SMEM_TOT>>>(edge_index, C, W_L1, W_L2,
                                             W_mlp1, W_mlp2, out, E);
}